// round 11
// baseline (speedup 1.0000x reference)
#include <cuda_runtime.h>
#include <cuda_fp16.h>
#include <cstdint>

#define N_B   256
#define D_K   1024
#define C_DIM 50000
#define G_N   4
#define NNZ_G 300000
#define E_TOT (G_N * NNZ_G)
#define NBLK_SCAN ((C_DIM + 255) / 256)   // 196

#define KC    64
#define NCH   (D_K / KC)                  // 16
#define TILE_C 128
#define NTILES ((C_DIM + TILE_C - 1) / TILE_C)  // 391
#define GEMM_SMEM 98304                   // 3 stages x (A 16K + B 16K)

// ---------------- scratch (static __device__, no allocs) ----------------
__device__ float  g_mean[D_K];
__device__ float  g_rstd[D_K];
__device__ __half g_Zh[(size_t)C_DIM * N_B];  // Z (fp16): gather + residual
// B image: per 64k-chunk, 256 m-rows x 128B fp16, SW128-swizzled
__device__ unsigned char g_B[NCH * N_B * 128];
// W image: per (c-tile, chunk), 128 rows x 128B fp16, SW128-swizzled (100 MB)
__device__ unsigned char g_Wh[(size_t)NTILES * NCH * 16384];

// CSR build scratch
__device__ int   g_cnt[C_DIM];
__device__ int   g_local[C_DIM];
__device__ int   g_bsum[256];
__device__ int   g_boff[256];
__device__ int   g_rowstart[C_DIM + 1];
__device__ int   g_cursor[C_DIM];
__device__ uint2 g_epack[E_TOT];           // (col, weight-bits)

// ---------------- helpers ----------------------------------------------
__device__ __forceinline__ uint32_t smem_u32(const void* p) {
    uint32_t a;
    asm("{ .reg .u64 t; cvta.to.shared.u64 t, %1; cvt.u32.u64 %0, t; }"
        : "=r"(a) : "l"(p));
    return a;
}
#define SW128(o) ((o) ^ (((o) >> 3) & 0x70))

#define LDSM4(f, addr) \
    asm volatile("ldmatrix.sync.aligned.m8n8.x4.shared.b16 {%0,%1,%2,%3}, [%4];" \
        : "=r"((f)[0]), "=r"((f)[1]), "=r"((f)[2]), "=r"((f)[3]) : "r"(addr))
#define LDSM2(f, addr) \
    asm volatile("ldmatrix.sync.aligned.m8n8.x2.shared.b16 {%0,%1}, [%2];" \
        : "=r"((f)[0]), "=r"((f)[1]) : "r"(addr))
#define MMAF16(d, a, b) \
    asm volatile("mma.sync.aligned.m16n8k16.row.col.f32.f16.f16.f32 " \
        "{%0,%1,%2,%3}, {%4,%5,%6,%7}, {%8,%9}, {%0,%1,%2,%3};" \
        : "+f"((d)[0]), "+f"((d)[1]), "+f"((d)[2]), "+f"((d)[3]) \
        : "r"((a)[0]), "r"((a)[1]), "r"((a)[2]), "r"((a)[3]), \
          "r"((b)[0]), "r"((b)[1]))
#define CP_ASYNC16(dst, src) \
    asm volatile("cp.async.cg.shared.global [%0], [%1], 16;" :: "r"(dst), "l"(src))
#define CP_COMMIT() asm volatile("cp.async.commit_group;" ::: "memory")
#define CP_WAIT0()  asm volatile("cp.async.wait_group 0;"  ::: "memory")
#define CP_WAIT1()  asm volatile("cp.async.wait_group 1;"  ::: "memory")

__device__ __forceinline__ uint32_t h2pack(float a, float b) {
    __half2 t = __floats2half2_rn(a, b);
    return *(uint32_t*)&t;
}
__device__ __forceinline__ float swishf(float h) {
    return h * (1.f / (1.f + __expf(-h)));
}

// -------- kernel 0: W fp32 -> fp16 pre-swizzled tile images -------------
__global__ void wconv_kernel(const float* __restrict__ W) {
    int id = blockIdx.x * 256 + threadIdx.x;
    int half = id & 1;
    int ch   = (id >> 1) & (NCH - 1);
    int rr   = id >> 5;                        // global c row
    int r    = rr & 127, tile = rr >> 7;
    bool valid = rr < C_DIM;
    const float* src = W + (size_t)rr * D_K + ch * KC + half * 32;
    unsigned char* base = g_Wh + ((size_t)tile * NCH + ch) * 16384 + r * 128;
    int rot = r & 7;
    #pragma unroll
    for (int j = 0; j < 4; j++) {
        float4 va = valid ? *(const float4*)(src + j * 8)
                          : make_float4(0.f, 0.f, 0.f, 0.f);
        float4 vb = valid ? *(const float4*)(src + j * 8 + 4)
                          : make_float4(0.f, 0.f, 0.f, 0.f);
        uint4 u = make_uint4(h2pack(va.x, va.y), h2pack(va.z, va.w),
                             h2pack(vb.x, vb.y), h2pack(vb.z, vb.w));
        *(uint4*)(base + (((half * 4 + j) ^ rot) << 4)) = u;
    }
}

// ---------------- kernel 1: batch stats (mean, rstd) --------------------
__global__ void stats_kernel(const float* __restrict__ x) {
    int tx = threadIdx.x & 31, ty = threadIdx.x >> 5;
    int c = blockIdx.x * 32 + tx;
    float s = 0.f, sq = 0.f;
    for (int r = ty; r < N_B; r += 8) {
        float v = x[r * D_K + c];
        s += v; sq += v * v;
    }
    __shared__ float ss[8][32], s2[8][32];
    ss[ty][tx] = s; s2[ty][tx] = sq;
    __syncthreads();
    if (ty == 0) {
        #pragma unroll
        for (int j = 1; j < 8; j++) { s += ss[j][tx]; sq += s2[j][tx]; }
        float mean = s * (1.f / N_B);
        float var  = sq * (1.f / N_B) - mean * mean;
        g_mean[c] = mean;
        g_rstd[c] = rsqrtf(var + 1e-5f);
    }
}

// ---------- kernel 2: normalize -> fp16 swizzled B image ----------------
__global__ void bconv_kernel(const float* __restrict__ x) {
    int id = blockIdx.x * 256 + threadIdx.x;   // 8192 threads
    int ch   = id >> 9;
    int m    = (id >> 1) & 255;
    int half = id & 1;
    int kb = ch * KC + half * 32;
    float v[32];
    #pragma unroll
    for (int q = 0; q < 8; q++) {
        float4 a  = *(const float4*)(x + m * D_K + kb + q * 4);
        float4 mu = *(const float4*)(g_mean + kb + q * 4);
        float4 rs = *(const float4*)(g_rstd + kb + q * 4);
        v[q * 4 + 0] = (a.x - mu.x) * rs.x;
        v[q * 4 + 1] = (a.y - mu.y) * rs.y;
        v[q * 4 + 2] = (a.z - mu.z) * rs.z;
        v[q * 4 + 3] = (a.w - mu.w) * rs.w;
    }
    unsigned char* base = g_B + (size_t)ch * (N_B * 128) + m * 128;
    int rot = m & 7;
    #pragma unroll
    for (int j = 0; j < 4; j++) {
        uint4 u = make_uint4(h2pack(v[8 * j + 0], v[8 * j + 1]),
                             h2pack(v[8 * j + 2], v[8 * j + 3]),
                             h2pack(v[8 * j + 4], v[8 * j + 5]),
                             h2pack(v[8 * j + 6], v[8 * j + 7]));
        *(uint4*)(base + (((half * 4 + j) ^ rot) << 4)) = u;
    }
}

// ------- kernel 3: fp16 mma.sync GEMM, bulk 3-stage pipeline ------------
__global__ __launch_bounds__(256, 2) void mma_gemm(const float* __restrict__ bias,
                                                   int m0) {
    extern __shared__ char smem[];
    uint32_t sb = smem_u32(smem);
    int tid = threadIdx.x, lane = tid & 31, warp = tid >> 5;
    int c0 = blockIdx.x * TILE_C;
    int warp_c = warp & 1, warp_m = warp >> 1;

    const unsigned char* gA = g_Wh + (size_t)blockIdx.x * NCH * 16384;
    const unsigned char* gB = g_B + (size_t)m0 * 128;   // per chunk: +ch*32768

    uint32_t a_row = (uint32_t)(warp_c * 64 + (lane & 7) + ((lane & 8) ? 8 : 0));
    uint32_t a_sel = (lane & 16) ? 16u : 0u;
    uint32_t b_row = (uint32_t)(warp_m * 32 + (lane & 7));
    uint32_t b_sel = (lane & 8) ? 16u : 0u;

    float acc[4][4][4];
    #pragma unroll
    for (int i = 0; i < 4; i++)
        #pragma unroll
        for (int j = 0; j < 4; j++)
            #pragma unroll
            for (int q = 0; q < 4; q++) acc[i][j][q] = 0.f;

    auto stage = [&](int s, int ch) {
        uint32_t dA = sb + s * 32768;
        uint32_t dB = dA + 16384;
        const unsigned char* sA = gA + (size_t)ch * 16384;
        const unsigned char* sB = gB + (size_t)ch * (N_B * 128);
        #pragma unroll
        for (int i = 0; i < 4; i++) {
            int u = (tid + 256 * i) * 16;
            CP_ASYNC16(dA + u, sA + u);
        }
        #pragma unroll
        for (int i = 0; i < 4; i++) {
            int u = (tid + 256 * i) * 16;
            CP_ASYNC16(dB + u, sB + u);
        }
        CP_COMMIT();
    };

    stage(0, 0);
    stage(1, 1);

    for (int ch = 0; ch < NCH; ch++) {
        if (ch < NCH - 2) CP_WAIT1(); else CP_WAIT0();
        __syncthreads();
        if (ch + 2 < NCH) stage((ch + 2) % 3, ch + 2);

        uint32_t Ab = sb + (ch % 3) * 32768;
        uint32_t Bb = Ab + 16384;
        #pragma unroll
        for (int s = 0; s < 4; s++) {
            uint32_t af[4][4], bf[4][2];
            #pragma unroll
            for (int t = 0; t < 4; t++) {
                uint32_t o = (a_row + t * 16) * 128 + s * 32 + a_sel;
                LDSM4(af[t], Ab + SW128(o));
            }
            #pragma unroll
            for (int t = 0; t < 4; t++) {
                uint32_t o = (b_row + t * 8) * 128 + s * 32 + b_sel;
                LDSM2(bf[t], Bb + SW128(o));
            }
            #pragma unroll
            for (int ct = 0; ct < 4; ct++)
                #pragma unroll
                for (int mt = 0; mt < 4; mt++)
                    MMAF16(acc[ct][mt], af[ct], bf[mt]);
        }
        __syncthreads();
    }

    // ---- epilogue: bias + swish -> Zh (fp16 only) ----
    #pragma unroll
    for (int ct = 0; ct < 4; ct++) {
        int crow = c0 + warp_c * 64 + ct * 16 + (lane >> 2);
        float bv0 = (crow < C_DIM) ? __ldg(bias + crow) : 0.f;
        float bv1 = (crow + 8 < C_DIM) ? __ldg(bias + crow + 8) : 0.f;
        #pragma unroll
        for (int mt = 0; mt < 4; mt++) {
            int m = m0 + warp_m * 32 + mt * 8 + 2 * (lane & 3);
            float* d = acc[ct][mt];
            if (crow < C_DIM) {
                float z0 = swishf(d[0] + bv0), z1 = swishf(d[1] + bv0);
                *(uint32_t*)(g_Zh + (size_t)crow * N_B + m) = h2pack(z0, z1);
            }
            if (crow + 8 < C_DIM) {
                float z2 = swishf(d[2] + bv1), z3 = swishf(d[3] + bv1);
                *(uint32_t*)(g_Zh + (size_t)(crow + 8) * N_B + m) =
                    h2pack(z2, z3);
            }
        }
    }
}

// ---------------- CSR build: zero, hist, scan x3, bucket-scatter --------
__global__ void zero_cnt_kernel() {
    int i = blockIdx.x * 256 + threadIdx.x;
    if (i < C_DIM) g_cnt[i] = 0;
}

__global__ void hist_kernel(const int* __restrict__ A_rows) {
    int e = blockIdx.x * 256 + threadIdx.x;
    if (e < E_TOT) atomicAdd(&g_cnt[A_rows[e]], 1);
}

__global__ void scan1_kernel() {
    int i = blockIdx.x * 256 + threadIdx.x;
    int v = (i < C_DIM) ? g_cnt[i] : 0;
    int lane = threadIdx.x & 31, w = threadIdx.x >> 5;
    int x = v;
    #pragma unroll
    for (int o = 1; o < 32; o <<= 1) {
        int y = __shfl_up_sync(~0u, x, o);
        if (lane >= o) x += y;
    }
    __shared__ int ws[8];
    if (lane == 31) ws[w] = x;
    __syncthreads();
    if (threadIdx.x < 8) {
        int s = ws[threadIdx.x];
        #pragma unroll
        for (int o = 1; o < 8; o <<= 1) {
            int y = __shfl_up_sync(0xff, s, o);
            if ((int)threadIdx.x >= o) s += y;
        }
        ws[threadIdx.x] = s;
    }
    __syncthreads();
    int off = (w > 0) ? ws[w - 1] : 0;
    int incl = x + off;
    if (i < C_DIM) g_local[i] = incl - v;
    if (threadIdx.x == 255) g_bsum[blockIdx.x] = incl;
}

__global__ void scan2_kernel() {
    int i = threadIdx.x;
    int v = (i < NBLK_SCAN) ? g_bsum[i] : 0;
    int lane = i & 31, w = i >> 5;
    int x = v;
    #pragma unroll
    for (int o = 1; o < 32; o <<= 1) {
        int y = __shfl_up_sync(~0u, x, o);
        if (lane >= o) x += y;
    }
    __shared__ int ws[8];
    if (lane == 31) ws[w] = x;
    __syncthreads();
    if (i < 8) {
        int s = ws[i];
        #pragma unroll
        for (int o = 1; o < 8; o <<= 1) {
            int y = __shfl_up_sync(0xff, s, o);
            if (i >= o) s += y;
        }
        ws[i] = s;
    }
    __syncthreads();
    int off = (w > 0) ? ws[w - 1] : 0;
    g_boff[i] = x + off - v;
}

__global__ void scan3_kernel() {
    int i = blockIdx.x * 256 + threadIdx.x;
    if (i < C_DIM) {
        int rs = g_local[i] + g_boff[i >> 8];
        g_rowstart[i] = rs;
        g_cursor[i]   = rs;
    }
    if (i == 0) g_rowstart[C_DIM] = E_TOT;
}

__global__ void build_kernel(const float* __restrict__ A_vals,
                             const float* __restrict__ vec,
                             const int* __restrict__ A_rows,
                             const int* __restrict__ A_cols) {
    int e = blockIdx.x * 256 + threadIdx.x;
    if (e >= E_TOT) return;
    int r = A_rows[e];
    int pos = atomicAdd(&g_cursor[r], 1);
    g_epack[pos] = make_uint2((uint32_t)A_cols[e],
                              __float_as_uint(A_vals[e] * __ldg(&vec[e / NNZ_G])));
}

// -- fused SpMM + transpose-out (one n-half): warp per row, fp16 gather --
__global__ __launch_bounds__(256) void spmm_out_kernel(float* __restrict__ out,
                                                       int nhalf) {
    __shared__ float sm[8][132];
    int wid = threadIdx.x >> 5, lane = threadIdx.x & 31;
    int row = blockIdx.x * 8 + wid;
    int beg = g_rowstart[row], end = g_rowstart[row + 1];
    const uint2* E = g_epack;
    const __half* Zb = g_Zh + nhalf * 128;

    // residual Z init from fp16 image; lane covers n-local = lane*4 .. +3
    float4 acc;
    {
        uint2 h = *(const uint2*)(Zb + (size_t)row * N_B + lane * 4);
        float2 a = __half22float2(*(__half2*)&h.x);
        float2 b = __half22float2(*(__half2*)&h.y);
        acc = make_float4(a.x, a.y, b.x, b.y);
    }

    int e = beg;
    for (; e + 4 <= end; e += 4) {
        uint2 p0 = E[e], p1 = E[e + 1], p2 = E[e + 2], p3 = E[e + 3];
        uint2 h0 = *(const uint2*)(Zb + (size_t)p0.x * N_B + lane * 4);
        uint2 h1 = *(const uint2*)(Zb + (size_t)p1.x * N_B + lane * 4);
        uint2 h2 = *(const uint2*)(Zb + (size_t)p2.x * N_B + lane * 4);
        uint2 h3 = *(const uint2*)(Zb + (size_t)p3.x * N_B + lane * 4);
        float w0 = __uint_as_float(p0.y), w1 = __uint_as_float(p1.y);
        float w2 = __uint_as_float(p2.y), w3 = __uint_as_float(p3.y);
        float2 a, b;
        a = __half22float2(*(__half2*)&h0.x); b = __half22float2(*(__half2*)&h0.y);
        acc.x = fmaf(w0, a.x, acc.x); acc.y = fmaf(w0, a.y, acc.y);
        acc.z = fmaf(w0, b.x, acc.z); acc.w = fmaf(w0, b.y, acc.w);
        a = __half22float2(*(__half2*)&h1.x); b = __half22float2(*(__half2*)&h1.y);
        acc.x = fmaf(w1, a.x, acc.x); acc.y = fmaf(w1, a.y, acc.y);
        acc.z = fmaf(w1, b.x, acc.z); acc.w = fmaf(w1, b.y, acc.w);
        a = __half22float2(*(__half2*)&h2.x); b = __half22float2(*(__half2*)&h2.y);
        acc.x = fmaf(w2, a.x, acc.x); acc.y = fmaf(w2, a.y, acc.y);
        acc.z = fmaf(w2, b.x, acc.z); acc.w = fmaf(w2, b.y, acc.w);
        a = __half22float2(*(__half2*)&h3.x); b = __half22float2(*(__half2*)&h3.y);
        acc.x = fmaf(w3, a.x, acc.x); acc.y = fmaf(w3, a.y, acc.y);
        acc.z = fmaf(w3, b.x, acc.z); acc.w = fmaf(w3, b.y, acc.w);
    }
    for (; e < end; e++) {
        uint2 p = E[e];
        float w = __uint_as_float(p.y);
        uint2 h = *(const uint2*)(Zb + (size_t)p.x * N_B + lane * 4);
        float2 a = __half22float2(*(__half2*)&h.x);
        float2 b = __half22float2(*(__half2*)&h.y);
        acc.x = fmaf(w, a.x, acc.x); acc.y = fmaf(w, a.y, acc.y);
        acc.z = fmaf(w, b.x, acc.z); acc.w = fmaf(w, b.y, acc.w);
    }

    // stage sm[c_local][n_local]
    sm[wid][lane * 4 + 0] = acc.x;
    sm[wid][lane * 4 + 1] = acc.y;
    sm[wid][lane * 4 + 2] = acc.z;
    sm[wid][lane * 4 + 3] = acc.w;
    __syncthreads();

    // transposed write: thread t -> n_local = t>>1, c quad = (t&1)*4
    int nl = threadIdx.x >> 1;
    int cq = (threadIdx.x & 1) * 4;
    float4 v = make_float4(sm[cq + 0][nl], sm[cq + 1][nl],
                           sm[cq + 2][nl], sm[cq + 3][nl]);
    *(float4*)(out + (size_t)(nhalf * 128 + nl) * C_DIM + blockIdx.x * 8 + cq) = v;
}

// ---------------- launch: 3-stream forked pipeline ----------------------
extern "C" void kernel_launch(void* const* d_in, const int* in_sizes, int n_in,
                              void* d_out, int out_size) {
    const float* output = (const float*)d_in[0];
    const float* wt2_w  = (const float*)d_in[1];
    const float* wt2_b  = (const float*)d_in[2];
    const float* A_vals = (const float*)d_in[3];
    const float* vec    = (const float*)d_in[4];
    const int*   A_rows = (const int*)d_in[5];
    const int*   A_cols = (const int*)d_in[6];
    float* out = (float*)d_out;

    static cudaStream_t sCsr = nullptr, sAux = nullptr, sB = nullptr;
    static cudaEvent_t evFork = nullptr, evCsr = nullptr, evG0 = nullptr,
                       evAux = nullptr, evB = nullptr;
    if (!sCsr) {
        cudaStreamCreateWithFlags(&sCsr, cudaStreamNonBlocking);
        cudaStreamCreateWithFlags(&sAux, cudaStreamNonBlocking);
        cudaStreamCreateWithFlags(&sB, cudaStreamNonBlocking);
        cudaEventCreateWithFlags(&evFork, cudaEventDisableTiming);
        cudaEventCreateWithFlags(&evCsr, cudaEventDisableTiming);
        cudaEventCreateWithFlags(&evG0, cudaEventDisableTiming);
        cudaEventCreateWithFlags(&evAux, cudaEventDisableTiming);
        cudaEventCreateWithFlags(&evB, cudaEventDisableTiming);
        cudaFuncSetAttribute(mma_gemm,
                             cudaFuncAttributeMaxDynamicSharedMemorySize,
                             GEMM_SMEM);
    }

    int egrid = (E_TOT + 255) / 256;
    int wgrid = (NTILES * 128 * NCH * 2) / 256;   // 6256

    cudaEventRecord(evFork, 0);
    cudaStreamWaitEvent(sCsr, evFork, 0);
    cudaStreamWaitEvent(sB, evFork, 0);

    // main: W image conversion (longest head kernel)
    wconv_kernel<<<wgrid, 256>>>(wt2_w);

    // sB: batch-norm stats + B image (independent of wconv)
    stats_kernel<<<D_K / 32, 256, 0, sB>>>(output);
    bconv_kernel<<<32, 256, 0, sB>>>(output);
    cudaEventRecord(evB, sB);

    // sCsr: CSR build (independent of dense chain)
    zero_cnt_kernel<<<NBLK_SCAN, 256, 0, sCsr>>>();
    hist_kernel<<<egrid, 256, 0, sCsr>>>(A_rows);
    scan1_kernel<<<NBLK_SCAN, 256, 0, sCsr>>>();
    scan2_kernel<<<1, 256, 0, sCsr>>>();
    scan3_kernel<<<NBLK_SCAN, 256, 0, sCsr>>>();
    build_kernel<<<egrid, 256, 0, sCsr>>>(A_vals, vec, A_rows, A_cols);
    cudaEventRecord(evCsr, sCsr);

    // main: GEMM halves (need wconv + bconv)
    cudaStreamWaitEvent(0, evB, 0);
    mma_gemm<<<NTILES, 256, GEMM_SMEM>>>(wt2_b, 0);
    cudaEventRecord(evG0, 0);
    mma_gemm<<<NTILES, 256, GEMM_SMEM>>>(wt2_b, 128);

    // aux: half-0 sparse work overlapped with gemm half-1
    cudaStreamWaitEvent(sAux, evG0, 0);
    cudaStreamWaitEvent(sAux, evCsr, 0);
    spmm_out_kernel<<<C_DIM / 8, 256, 0, sAux>>>(out, 0);
    cudaEventRecord(evAux, sAux);

    // main: half-1 sparse work after gemm half-1
    cudaStreamWaitEvent(0, evCsr, 0);
    spmm_out_kernel<<<C_DIM / 8, 256>>>(out, 1);

    cudaStreamWaitEvent(0, evAux, 0);
}

// round 12
// speedup vs baseline: 1.4362x; 1.4362x over previous
#include <cuda_runtime.h>
#include <cuda_fp16.h>
#include <cstdint>

#define N_B   256
#define D_K   1024
#define C_DIM 50000
#define G_N   4
#define NNZ_G 300000
#define E_TOT (G_N * NNZ_G)
#define NBLK_SCAN ((C_DIM + 255) / 256)   // 196

#define KC    64
#define NCH   (D_K / KC)                  // 16
#define TILE_C 128
#define NTILES ((C_DIM + TILE_C - 1) / TILE_C)  // 391
#define GEMM_SMEM 98304                   // 3 stages x (A 16K + B 16K)

// ---------------- scratch (static __device__, no allocs) ----------------
__device__ float  g_mean[D_K];
__device__ float  g_rstd[D_K];
__device__ __half g_Zh[(size_t)C_DIM * N_B];  // Z (fp16): gather + residual
// B image: per 64k-chunk, 256 m-rows x 128B fp16, SW128-swizzled
__device__ unsigned char g_B[NCH * N_B * 128];
// W image: per (c-tile, chunk), 128 rows x 128B fp16, SW128-swizzled (100 MB)
__device__ unsigned char g_Wh[(size_t)NTILES * NCH * 16384];

// CSR build scratch
__device__ int   g_cnt[C_DIM];
__device__ int   g_local[C_DIM];
__device__ int   g_bsum[256];
__device__ int   g_boff[256];
__device__ int   g_rowstart[C_DIM + 1];
__device__ int   g_cursor[C_DIM];
__device__ uint2 g_epack[E_TOT];           // (col, weight-bits)

// ---------------- helpers ----------------------------------------------
__device__ __forceinline__ uint32_t smem_u32(const void* p) {
    uint32_t a;
    asm("{ .reg .u64 t; cvta.to.shared.u64 t, %1; cvt.u32.u64 %0, t; }"
        : "=r"(a) : "l"(p));
    return a;
}
#define SW128(o) ((o) ^ (((o) >> 3) & 0x70))

#define LDSM4(f, addr) \
    asm volatile("ldmatrix.sync.aligned.m8n8.x4.shared.b16 {%0,%1,%2,%3}, [%4];" \
        : "=r"((f)[0]), "=r"((f)[1]), "=r"((f)[2]), "=r"((f)[3]) : "r"(addr))
#define LDSM2(f, addr) \
    asm volatile("ldmatrix.sync.aligned.m8n8.x2.shared.b16 {%0,%1}, [%2];" \
        : "=r"((f)[0]), "=r"((f)[1]) : "r"(addr))
#define MMAF16(d, a, b) \
    asm volatile("mma.sync.aligned.m16n8k16.row.col.f32.f16.f16.f32 " \
        "{%0,%1,%2,%3}, {%4,%5,%6,%7}, {%8,%9}, {%0,%1,%2,%3};" \
        : "+f"((d)[0]), "+f"((d)[1]), "+f"((d)[2]), "+f"((d)[3]) \
        : "r"((a)[0]), "r"((a)[1]), "r"((a)[2]), "r"((a)[3]), \
          "r"((b)[0]), "r"((b)[1]))
#define CP_ASYNC16(dst, src) \
    asm volatile("cp.async.cg.shared.global [%0], [%1], 16;" :: "r"(dst), "l"(src))
#define CP_COMMIT() asm volatile("cp.async.commit_group;" ::: "memory")
#define CP_WAIT0()  asm volatile("cp.async.wait_group 0;"  ::: "memory")
#define CP_WAIT1()  asm volatile("cp.async.wait_group 1;"  ::: "memory")

__device__ __forceinline__ uint32_t h2pack(float a, float b) {
    __half2 t = __floats2half2_rn(a, b);
    return *(uint32_t*)&t;
}
__device__ __forceinline__ float swishf(float h) {
    return h * (1.f / (1.f + __expf(-h)));
}

// -------- kernel 0: W fp32 -> fp16 pre-swizzled tile images -------------
__global__ void wconv_kernel(const float* __restrict__ W) {
    int id = blockIdx.x * 256 + threadIdx.x;
    int half = id & 1;
    int ch   = (id >> 1) & (NCH - 1);
    int rr   = id >> 5;                        // global c row
    int r    = rr & 127, tile = rr >> 7;
    bool valid = rr < C_DIM;
    const float* src = W + (size_t)rr * D_K + ch * KC + half * 32;
    unsigned char* base = g_Wh + ((size_t)tile * NCH + ch) * 16384 + r * 128;
    int rot = r & 7;
    #pragma unroll
    for (int j = 0; j < 4; j++) {
        float4 va = valid ? *(const float4*)(src + j * 8)
                          : make_float4(0.f, 0.f, 0.f, 0.f);
        float4 vb = valid ? *(const float4*)(src + j * 8 + 4)
                          : make_float4(0.f, 0.f, 0.f, 0.f);
        uint4 u = make_uint4(h2pack(va.x, va.y), h2pack(va.z, va.w),
                             h2pack(vb.x, vb.y), h2pack(vb.z, vb.w));
        *(uint4*)(base + (((half * 4 + j) ^ rot) << 4)) = u;
    }
}

// ---------------- kernel 1: batch stats (mean, rstd) --------------------
__global__ void stats_kernel(const float* __restrict__ x) {
    int tx = threadIdx.x & 31, ty = threadIdx.x >> 5;
    int c = blockIdx.x * 32 + tx;
    float s = 0.f, sq = 0.f;
    for (int r = ty; r < N_B; r += 8) {
        float v = x[r * D_K + c];
        s += v; sq += v * v;
    }
    __shared__ float ss[8][32], s2[8][32];
    ss[ty][tx] = s; s2[ty][tx] = sq;
    __syncthreads();
    if (ty == 0) {
        #pragma unroll
        for (int j = 1; j < 8; j++) { s += ss[j][tx]; sq += s2[j][tx]; }
        float mean = s * (1.f / N_B);
        float var  = sq * (1.f / N_B) - mean * mean;
        g_mean[c] = mean;
        g_rstd[c] = rsqrtf(var + 1e-5f);
    }
}

// ---------- kernel 2: normalize -> fp16 swizzled B image ----------------
__global__ void bconv_kernel(const float* __restrict__ x) {
    int id = blockIdx.x * 256 + threadIdx.x;   // 8192 threads
    int ch   = id >> 9;
    int m    = (id >> 1) & 255;
    int half = id & 1;
    int kb = ch * KC + half * 32;
    float v[32];
    #pragma unroll
    for (int q = 0; q < 8; q++) {
        float4 a  = *(const float4*)(x + m * D_K + kb + q * 4);
        float4 mu = *(const float4*)(g_mean + kb + q * 4);
        float4 rs = *(const float4*)(g_rstd + kb + q * 4);
        v[q * 4 + 0] = (a.x - mu.x) * rs.x;
        v[q * 4 + 1] = (a.y - mu.y) * rs.y;
        v[q * 4 + 2] = (a.z - mu.z) * rs.z;
        v[q * 4 + 3] = (a.w - mu.w) * rs.w;
    }
    unsigned char* base = g_B + (size_t)ch * (N_B * 128) + m * 128;
    int rot = m & 7;
    #pragma unroll
    for (int j = 0; j < 4; j++) {
        uint4 u = make_uint4(h2pack(v[8 * j + 0], v[8 * j + 1]),
                             h2pack(v[8 * j + 2], v[8 * j + 3]),
                             h2pack(v[8 * j + 4], v[8 * j + 5]),
                             h2pack(v[8 * j + 6], v[8 * j + 7]));
        *(uint4*)(base + (((half * 4 + j) ^ rot) << 4)) = u;
    }
}

// ------- kernel 3: fp16 mma.sync GEMM, bulk 3-stage pipeline ------------
__global__ __launch_bounds__(256, 2) void mma_gemm(const float* __restrict__ bias,
                                                   int m0) {
    extern __shared__ char smem[];
    uint32_t sb = smem_u32(smem);
    int tid = threadIdx.x, lane = tid & 31, warp = tid >> 5;
    int c0 = blockIdx.x * TILE_C;
    int warp_c = warp & 1, warp_m = warp >> 1;

    const unsigned char* gA = g_Wh + (size_t)blockIdx.x * NCH * 16384;
    const unsigned char* gB = g_B + (size_t)m0 * 128;   // per chunk: +ch*32768

    uint32_t a_row = (uint32_t)(warp_c * 64 + (lane & 7) + ((lane & 8) ? 8 : 0));
    uint32_t a_sel = (lane & 16) ? 16u : 0u;
    uint32_t b_row = (uint32_t)(warp_m * 32 + (lane & 7));
    uint32_t b_sel = (lane & 8) ? 16u : 0u;

    float acc[4][4][4];
    #pragma unroll
    for (int i = 0; i < 4; i++)
        #pragma unroll
        for (int j = 0; j < 4; j++)
            #pragma unroll
            for (int q = 0; q < 4; q++) acc[i][j][q] = 0.f;

    auto stage = [&](int s, int ch) {
        uint32_t dA = sb + s * 32768;
        uint32_t dB = dA + 16384;
        const unsigned char* sA = gA + (size_t)ch * 16384;
        const unsigned char* sB = gB + (size_t)ch * (N_B * 128);
        #pragma unroll
        for (int i = 0; i < 4; i++) {
            int u = (tid + 256 * i) * 16;
            CP_ASYNC16(dA + u, sA + u);
        }
        #pragma unroll
        for (int i = 0; i < 4; i++) {
            int u = (tid + 256 * i) * 16;
            CP_ASYNC16(dB + u, sB + u);
        }
        CP_COMMIT();
    };

    stage(0, 0);
    stage(1, 1);

    for (int ch = 0; ch < NCH; ch++) {
        if (ch < NCH - 2) CP_WAIT1(); else CP_WAIT0();
        __syncthreads();
        if (ch + 2 < NCH) stage((ch + 2) % 3, ch + 2);

        uint32_t Ab = sb + (ch % 3) * 32768;
        uint32_t Bb = Ab + 16384;
        #pragma unroll
        for (int s = 0; s < 4; s++) {
            uint32_t af[4][4], bf[4][2];
            #pragma unroll
            for (int t = 0; t < 4; t++) {
                uint32_t o = (a_row + t * 16) * 128 + s * 32 + a_sel;
                LDSM4(af[t], Ab + SW128(o));
            }
            #pragma unroll
            for (int t = 0; t < 4; t++) {
                uint32_t o = (b_row + t * 8) * 128 + s * 32 + b_sel;
                LDSM2(bf[t], Bb + SW128(o));
            }
            #pragma unroll
            for (int ct = 0; ct < 4; ct++)
                #pragma unroll
                for (int mt = 0; mt < 4; mt++)
                    MMAF16(acc[ct][mt], af[ct], bf[mt]);
        }
        __syncthreads();
    }

    // ---- epilogue: bias + swish -> Zh (fp16 only; no fp32 copy) ----
    #pragma unroll
    for (int ct = 0; ct < 4; ct++) {
        int crow = c0 + warp_c * 64 + ct * 16 + (lane >> 2);
        float bv0 = (crow < C_DIM) ? __ldg(bias + crow) : 0.f;
        float bv1 = (crow + 8 < C_DIM) ? __ldg(bias + crow + 8) : 0.f;
        #pragma unroll
        for (int mt = 0; mt < 4; mt++) {
            int m = m0 + warp_m * 32 + mt * 8 + 2 * (lane & 3);
            float* d = acc[ct][mt];
            if (crow < C_DIM) {
                float z0 = swishf(d[0] + bv0), z1 = swishf(d[1] + bv0);
                *(uint32_t*)(g_Zh + (size_t)crow * N_B + m) = h2pack(z0, z1);
            }
            if (crow + 8 < C_DIM) {
                float z2 = swishf(d[2] + bv1), z3 = swishf(d[3] + bv1);
                *(uint32_t*)(g_Zh + (size_t)(crow + 8) * N_B + m) =
                    h2pack(z2, z3);
            }
        }
    }
}

// ---------------- CSR build: zero, hist, scan x3, bucket-scatter --------
__global__ void zero_cnt_kernel() {
    int i = blockIdx.x * 256 + threadIdx.x;
    if (i < C_DIM) g_cnt[i] = 0;
}

__global__ void hist_kernel(const int* __restrict__ A_rows) {
    int e = blockIdx.x * 256 + threadIdx.x;
    if (e < E_TOT) atomicAdd(&g_cnt[A_rows[e]], 1);
}

__global__ void scan1_kernel() {
    int i = blockIdx.x * 256 + threadIdx.x;
    int v = (i < C_DIM) ? g_cnt[i] : 0;
    int lane = threadIdx.x & 31, w = threadIdx.x >> 5;
    int x = v;
    #pragma unroll
    for (int o = 1; o < 32; o <<= 1) {
        int y = __shfl_up_sync(~0u, x, o);
        if (lane >= o) x += y;
    }
    __shared__ int ws[8];
    if (lane == 31) ws[w] = x;
    __syncthreads();
    if (threadIdx.x < 8) {
        int s = ws[threadIdx.x];
        #pragma unroll
        for (int o = 1; o < 8; o <<= 1) {
            int y = __shfl_up_sync(0xff, s, o);
            if ((int)threadIdx.x >= o) s += y;
        }
        ws[threadIdx.x] = s;
    }
    __syncthreads();
    int off = (w > 0) ? ws[w - 1] : 0;
    int incl = x + off;
    if (i < C_DIM) g_local[i] = incl - v;
    if (threadIdx.x == 255) g_bsum[blockIdx.x] = incl;
}

__global__ void scan2_kernel() {
    int i = threadIdx.x;
    int v = (i < NBLK_SCAN) ? g_bsum[i] : 0;
    int lane = i & 31, w = i >> 5;
    int x = v;
    #pragma unroll
    for (int o = 1; o < 32; o <<= 1) {
        int y = __shfl_up_sync(~0u, x, o);
        if (lane >= o) x += y;
    }
    __shared__ int ws[8];
    if (lane == 31) ws[w] = x;
    __syncthreads();
    if (i < 8) {
        int s = ws[i];
        #pragma unroll
        for (int o = 1; o < 8; o <<= 1) {
            int y = __shfl_up_sync(0xff, s, o);
            if (i >= o) s += y;
        }
        ws[i] = s;
    }
    __syncthreads();
    int off = (w > 0) ? ws[w - 1] : 0;
    g_boff[i] = x + off - v;
}

__global__ void scan3_kernel() {
    int i = blockIdx.x * 256 + threadIdx.x;
    if (i < C_DIM) {
        int rs = g_local[i] + g_boff[i >> 8];
        g_rowstart[i] = rs;
        g_cursor[i]   = rs;
    }
    if (i == 0) g_rowstart[C_DIM] = E_TOT;
}

__global__ void build_kernel(const float* __restrict__ A_vals,
                             const float* __restrict__ vec,
                             const int* __restrict__ A_rows,
                             const int* __restrict__ A_cols) {
    int e = blockIdx.x * 256 + threadIdx.x;
    if (e >= E_TOT) return;
    int r = A_rows[e];
    int pos = atomicAdd(&g_cursor[r], 1);
    g_epack[pos] = make_uint2((uint32_t)A_cols[e],
                              __float_as_uint(A_vals[e] * __ldg(&vec[e / NNZ_G])));
}

// -- fused SpMM + transpose-out (one n-half): warp per row, fp16 gather --
__global__ __launch_bounds__(256) void spmm_out_kernel(float* __restrict__ out,
                                                       int nhalf) {
    __shared__ float sm[8][132];
    int wid = threadIdx.x >> 5, lane = threadIdx.x & 31;
    int row = blockIdx.x * 8 + wid;
    int beg = g_rowstart[row], end = g_rowstart[row + 1];
    const uint2* E = g_epack;
    const __half* Zb = g_Zh + nhalf * 128;

    // residual Z init from fp16 image; lane covers n-local = lane*4 .. +3
    float4 acc;
    {
        uint2 h = *(const uint2*)(Zb + (size_t)row * N_B + lane * 4);
        float2 a = __half22float2(*(__half2*)&h.x);
        float2 b = __half22float2(*(__half2*)&h.y);
        acc = make_float4(a.x, a.y, b.x, b.y);
    }

    int e = beg;
    for (; e + 4 <= end; e += 4) {
        uint2 p0 = E[e], p1 = E[e + 1], p2 = E[e + 2], p3 = E[e + 3];
        uint2 h0 = *(const uint2*)(Zb + (size_t)p0.x * N_B + lane * 4);
        uint2 h1 = *(const uint2*)(Zb + (size_t)p1.x * N_B + lane * 4);
        uint2 h2 = *(const uint2*)(Zb + (size_t)p2.x * N_B + lane * 4);
        uint2 h3 = *(const uint2*)(Zb + (size_t)p3.x * N_B + lane * 4);
        float w0 = __uint_as_float(p0.y), w1 = __uint_as_float(p1.y);
        float w2 = __uint_as_float(p2.y), w3 = __uint_as_float(p3.y);
        float2 a, b;
        a = __half22float2(*(__half2*)&h0.x); b = __half22float2(*(__half2*)&h0.y);
        acc.x = fmaf(w0, a.x, acc.x); acc.y = fmaf(w0, a.y, acc.y);
        acc.z = fmaf(w0, b.x, acc.z); acc.w = fmaf(w0, b.y, acc.w);
        a = __half22float2(*(__half2*)&h1.x); b = __half22float2(*(__half2*)&h1.y);
        acc.x = fmaf(w1, a.x, acc.x); acc.y = fmaf(w1, a.y, acc.y);
        acc.z = fmaf(w1, b.x, acc.z); acc.w = fmaf(w1, b.y, acc.w);
        a = __half22float2(*(__half2*)&h2.x); b = __half22float2(*(__half2*)&h2.y);
        acc.x = fmaf(w2, a.x, acc.x); acc.y = fmaf(w2, a.y, acc.y);
        acc.z = fmaf(w2, b.x, acc.z); acc.w = fmaf(w2, b.y, acc.w);
        a = __half22float2(*(__half2*)&h3.x); b = __half22float2(*(__half2*)&h3.y);
        acc.x = fmaf(w3, a.x, acc.x); acc.y = fmaf(w3, a.y, acc.y);
        acc.z = fmaf(w3, b.x, acc.z); acc.w = fmaf(w3, b.y, acc.w);
    }
    for (; e < end; e++) {
        uint2 p = E[e];
        float w = __uint_as_float(p.y);
        uint2 h = *(const uint2*)(Zb + (size_t)p.x * N_B + lane * 4);
        float2 a = __half22float2(*(__half2*)&h.x);
        float2 b = __half22float2(*(__half2*)&h.y);
        acc.x = fmaf(w, a.x, acc.x); acc.y = fmaf(w, a.y, acc.y);
        acc.z = fmaf(w, b.x, acc.z); acc.w = fmaf(w, b.y, acc.w);
    }

    // stage sm[c_local][n_local]
    sm[wid][lane * 4 + 0] = acc.x;
    sm[wid][lane * 4 + 1] = acc.y;
    sm[wid][lane * 4 + 2] = acc.z;
    sm[wid][lane * 4 + 3] = acc.w;
    __syncthreads();

    // transposed write: thread t -> n_local = t>>1, c quad = (t&1)*4
    int nl = threadIdx.x >> 1;
    int cq = (threadIdx.x & 1) * 4;
    float4 v = make_float4(sm[cq + 0][nl], sm[cq + 1][nl],
                           sm[cq + 2][nl], sm[cq + 3][nl]);
    *(float4*)(out + (size_t)(nhalf * 128 + nl) * C_DIM + blockIdx.x * 8 + cq) = v;
}

// ------- launch: EXACT round-9 structure (2 forked streams) -------------
extern "C" void kernel_launch(void* const* d_in, const int* in_sizes, int n_in,
                              void* d_out, int out_size) {
    const float* output = (const float*)d_in[0];
    const float* wt2_w  = (const float*)d_in[1];
    const float* wt2_b  = (const float*)d_in[2];
    const float* A_vals = (const float*)d_in[3];
    const float* vec    = (const float*)d_in[4];
    const int*   A_rows = (const int*)d_in[5];
    const int*   A_cols = (const int*)d_in[6];
    float* out = (float*)d_out;

    static cudaStream_t sCsr = nullptr, sAux = nullptr;
    static cudaEvent_t evFork = nullptr, evCsr = nullptr, evG0 = nullptr,
                       evAux = nullptr;
    if (!sCsr) {
        cudaStreamCreateWithFlags(&sCsr, cudaStreamNonBlocking);
        cudaStreamCreateWithFlags(&sAux, cudaStreamNonBlocking);
        cudaEventCreateWithFlags(&evFork, cudaEventDisableTiming);
        cudaEventCreateWithFlags(&evCsr, cudaEventDisableTiming);
        cudaEventCreateWithFlags(&evG0, cudaEventDisableTiming);
        cudaEventCreateWithFlags(&evAux, cudaEventDisableTiming);
        cudaFuncSetAttribute(mma_gemm,
                             cudaFuncAttributeMaxDynamicSharedMemorySize,
                             GEMM_SMEM);
    }

    int egrid = (E_TOT + 255) / 256;
    int wgrid = (NTILES * 128 * NCH * 2) / 256;   // 6256

    cudaEventRecord(evFork, 0);
    cudaStreamWaitEvent(sCsr, evFork, 0);

    // main stream, round-9 order: gemm0 at kernel index 3 for ncu
    wconv_kernel<<<wgrid, 256>>>(wt2_w);                           // 0
    stats_kernel<<<D_K / 32, 256>>>(output);                       // 1
    bconv_kernel<<<32, 256>>>(output);                             // 2
    mma_gemm<<<NTILES, 256, GEMM_SMEM>>>(wt2_b, 0);                // 3 <- ncu
    cudaEventRecord(evG0, 0);

    zero_cnt_kernel<<<NBLK_SCAN, 256, 0, sCsr>>>();
    hist_kernel<<<egrid, 256, 0, sCsr>>>(A_rows);
    scan1_kernel<<<NBLK_SCAN, 256, 0, sCsr>>>();
    scan2_kernel<<<1, 256, 0, sCsr>>>();
    scan3_kernel<<<NBLK_SCAN, 256, 0, sCsr>>>();
    build_kernel<<<egrid, 256, 0, sCsr>>>(A_vals, vec, A_rows, A_cols);
    cudaEventRecord(evCsr, sCsr);

    mma_gemm<<<NTILES, 256, GEMM_SMEM>>>(wt2_b, 128);

    // aux: half-0 sparse work overlapped with gemm half-1
    cudaStreamWaitEvent(sAux, evG0, 0);
    cudaStreamWaitEvent(sAux, evCsr, 0);
    spmm_out_kernel<<<C_DIM / 8, 256, 0, sAux>>>(out, 0);
    cudaEventRecord(evAux, sAux);

    // main: half-1 sparse work after gemm half-1
    cudaStreamWaitEvent(0, evCsr, 0);
    spmm_out_kernel<<<C_DIM / 8, 256>>>(out, 1);

    cudaStreamWaitEvent(0, evAux, 0);
}

// round 15
// speedup vs baseline: 1.5323x; 1.0669x over previous
#include <cuda_runtime.h>
#include <cuda_fp16.h>
#include <cstdint>

#define N_B   256
#define D_K   1024
#define C_DIM 50000
#define G_N   4
#define NNZ_G 300000
#define E_TOT (G_N * NNZ_G)
#define NBLK_SCAN ((C_DIM + 255) / 256)   // 196

#define KC    64
#define NCH   (D_K / KC)                  // 16
#define TILE_C 128
#define NTILES ((C_DIM + TILE_C - 1) / TILE_C)  // 391
#define GEMM_SMEM 98304                   // 3 stages x (A 16K + B 16K)

// ---------------- scratch (static __device__, no allocs) ----------------
__device__ float  g_mean[D_K];
__device__ float  g_rstd[D_K];
__device__ __half g_Zh[(size_t)C_DIM * N_B];  // Z (fp16): gather + residual
// B image: per 64k-chunk, 256 m-rows x 128B fp16, SW128-swizzled
__device__ unsigned char g_B[NCH * N_B * 128];
// W image: per (c-tile, chunk), 128 rows x 128B fp16, SW128-swizzled (100 MB)
__device__ unsigned char g_Wh[(size_t)NTILES * NCH * 16384];

// CSR build scratch
__device__ int   g_cnt[C_DIM];
__device__ int   g_local[C_DIM];
__device__ int   g_bsum[256];
__device__ int   g_boff[256];
__device__ int   g_rowstart[C_DIM + 1];
__device__ int   g_cursor[C_DIM];
__device__ uint2 g_epack[E_TOT];           // (col, weight-bits)

// ---------------- helpers ----------------------------------------------
__device__ __forceinline__ uint32_t smem_u32(const void* p) {
    uint32_t a;
    asm("{ .reg .u64 t; cvta.to.shared.u64 t, %1; cvt.u32.u64 %0, t; }"
        : "=r"(a) : "l"(p));
    return a;
}
#define SW128(o) ((o) ^ (((o) >> 3) & 0x70))

#define LDSM4(f, addr) \
    asm volatile("ldmatrix.sync.aligned.m8n8.x4.shared.b16 {%0,%1,%2,%3}, [%4];" \
        : "=r"((f)[0]), "=r"((f)[1]), "=r"((f)[2]), "=r"((f)[3]) : "r"(addr))
#define LDSM2(f, addr) \
    asm volatile("ldmatrix.sync.aligned.m8n8.x2.shared.b16 {%0,%1}, [%2];" \
        : "=r"((f)[0]), "=r"((f)[1]) : "r"(addr))
#define MMAF16(d, a, b) \
    asm volatile("mma.sync.aligned.m16n8k16.row.col.f32.f16.f16.f32 " \
        "{%0,%1,%2,%3}, {%4,%5,%6,%7}, {%8,%9}, {%0,%1,%2,%3};" \
        : "+f"((d)[0]), "+f"((d)[1]), "+f"((d)[2]), "+f"((d)[3]) \
        : "r"((a)[0]), "r"((a)[1]), "r"((a)[2]), "r"((a)[3]), \
          "r"((b)[0]), "r"((b)[1]))
#define CP_ASYNC16(dst, src) \
    asm volatile("cp.async.cg.shared.global [%0], [%1], 16;" :: "r"(dst), "l"(src))
#define CP_COMMIT() asm volatile("cp.async.commit_group;" ::: "memory")
#define CP_WAIT0()  asm volatile("cp.async.wait_group 0;"  ::: "memory")
#define CP_WAIT1()  asm volatile("cp.async.wait_group 1;"  ::: "memory")

__device__ __forceinline__ uint32_t h2pack(float a, float b) {
    __half2 t = __floats2half2_rn(a, b);
    return *(uint32_t*)&t;
}
__device__ __forceinline__ float swishf(float h) {
    return h * (1.f / (1.f + __expf(-h)));
}

// -------- kernel 0: W fp32 -> fp16 pre-swizzled tile images -------------
// One 16B output unit per thread; warp writes contiguous 512B.
__global__ void wconv_kernel(const float* __restrict__ W) {
    int id = blockIdx.x * 256 + threadIdx.x;   // NTILES*NCH*128*8 ids
    int j    = id & 7;                          // 16B unit within row
    int r    = (id >> 3) & 127;                 // row within tile
    int ch   = (id >> 10) & (NCH - 1);
    int tile = id >> 14;
    int rr   = tile * 128 + r;
    bool valid = rr < C_DIM;
    const float* src = W + (size_t)rr * D_K + ch * KC + j * 8;
    float4 va = valid ? *(const float4*)(src)     : make_float4(0.f, 0.f, 0.f, 0.f);
    float4 vb = valid ? *(const float4*)(src + 4) : make_float4(0.f, 0.f, 0.f, 0.f);
    uint4 u = make_uint4(h2pack(va.x, va.y), h2pack(va.z, va.w),
                         h2pack(vb.x, vb.y), h2pack(vb.z, vb.w));
    unsigned char* base = g_Wh + ((size_t)tile * NCH + ch) * 16384 + r * 128;
    int rot = r & 7;
    *(uint4*)(base + ((j ^ rot) << 4)) = u;
}

// ---------------- kernel 1: batch stats (mean, rstd) --------------------
__global__ void stats_kernel(const float* __restrict__ x) {
    int tx = threadIdx.x & 31, ty = threadIdx.x >> 5;
    int c = blockIdx.x * 32 + tx;
    float s = 0.f, sq = 0.f;
    for (int r = ty; r < N_B; r += 8) {
        float v = x[r * D_K + c];
        s += v; sq += v * v;
    }
    __shared__ float ss[8][32], s2[8][32];
    ss[ty][tx] = s; s2[ty][tx] = sq;
    __syncthreads();
    if (ty == 0) {
        #pragma unroll
        for (int j = 1; j < 8; j++) { s += ss[j][tx]; sq += s2[j][tx]; }
        float mean = s * (1.f / N_B);
        float var  = sq * (1.f / N_B) - mean * mean;
        g_mean[c] = mean;
        g_rstd[c] = rsqrtf(var + 1e-5f);
    }
}

// ---------- kernel 2: normalize -> fp16 swizzled B image ----------------
__global__ void bconv_kernel(const float* __restrict__ x) {
    int id = blockIdx.x * 256 + threadIdx.x;   // 8192 threads
    int ch   = id >> 9;
    int m    = (id >> 1) & 255;
    int half = id & 1;
    int kb = ch * KC + half * 32;
    float v[32];
    #pragma unroll
    for (int q = 0; q < 8; q++) {
        float4 a  = *(const float4*)(x + m * D_K + kb + q * 4);
        float4 mu = *(const float4*)(g_mean + kb + q * 4);
        float4 rs = *(const float4*)(g_rstd + kb + q * 4);
        v[q * 4 + 0] = (a.x - mu.x) * rs.x;
        v[q * 4 + 1] = (a.y - mu.y) * rs.y;
        v[q * 4 + 2] = (a.z - mu.z) * rs.z;
        v[q * 4 + 3] = (a.w - mu.w) * rs.w;
    }
    unsigned char* base = g_B + (size_t)ch * (N_B * 128) + m * 128;
    int rot = m & 7;
    #pragma unroll
    for (int j = 0; j < 4; j++) {
        uint4 u = make_uint4(h2pack(v[8 * j + 0], v[8 * j + 1]),
                             h2pack(v[8 * j + 2], v[8 * j + 3]),
                             h2pack(v[8 * j + 4], v[8 * j + 5]),
                             h2pack(v[8 * j + 6], v[8 * j + 7]));
        *(uint4*)(base + (((half * 4 + j) ^ rot) << 4)) = u;
    }
}

// ------- kernel 3: fp16 mma.sync GEMM, bulk 3-stage pipeline ------------
__global__ __launch_bounds__(256, 2) void mma_gemm(const float* __restrict__ bias,
                                                   int m0) {
    extern __shared__ char smem[];
    uint32_t sb = smem_u32(smem);
    int tid = threadIdx.x, lane = tid & 31, warp = tid >> 5;
    int c0 = blockIdx.x * TILE_C;
    int warp_c = warp & 1, warp_m = warp >> 1;

    const unsigned char* gA = g_Wh + (size_t)blockIdx.x * NCH * 16384;
    const unsigned char* gB = g_B + (size_t)m0 * 128;   // per chunk: +ch*32768

    uint32_t a_row = (uint32_t)(warp_c * 64 + (lane & 7) + ((lane & 8) ? 8 : 0));
    uint32_t a_sel = (lane & 16) ? 16u : 0u;
    uint32_t b_row = (uint32_t)(warp_m * 32 + (lane & 7));
    uint32_t b_sel = (lane & 8) ? 16u : 0u;

    float acc[4][4][4];
    #pragma unroll
    for (int i = 0; i < 4; i++)
        #pragma unroll
        for (int j = 0; j < 4; j++)
            #pragma unroll
            for (int q = 0; q < 4; q++) acc[i][j][q] = 0.f;

    auto stage = [&](int s, int ch) {
        uint32_t dA = sb + s * 32768;
        uint32_t dB = dA + 16384;
        const unsigned char* sA = gA + (size_t)ch * 16384;
        const unsigned char* sB = gB + (size_t)ch * (N_B * 128);
        #pragma unroll
        for (int i = 0; i < 4; i++) {
            int u = (tid + 256 * i) * 16;
            CP_ASYNC16(dA + u, sA + u);
        }
        #pragma unroll
        for (int i = 0; i < 4; i++) {
            int u = (tid + 256 * i) * 16;
            CP_ASYNC16(dB + u, sB + u);
        }
        CP_COMMIT();
    };

    stage(0, 0);
    stage(1, 1);

    for (int ch = 0; ch < NCH; ch++) {
        if (ch < NCH - 2) CP_WAIT1(); else CP_WAIT0();
        __syncthreads();
        if (ch + 2 < NCH) stage((ch + 2) % 3, ch + 2);

        uint32_t Ab = sb + (ch % 3) * 32768;
        uint32_t Bb = Ab + 16384;
        #pragma unroll
        for (int s = 0; s < 4; s++) {
            uint32_t af[4][4], bf[4][2];
            #pragma unroll
            for (int t = 0; t < 4; t++) {
                uint32_t o = (a_row + t * 16) * 128 + s * 32 + a_sel;
                LDSM4(af[t], Ab + SW128(o));
            }
            #pragma unroll
            for (int t = 0; t < 4; t++) {
                uint32_t o = (b_row + t * 8) * 128 + s * 32 + b_sel;
                LDSM2(bf[t], Bb + SW128(o));
            }
            #pragma unroll
            for (int ct = 0; ct < 4; ct++)
                #pragma unroll
                for (int mt = 0; mt < 4; mt++)
                    MMAF16(acc[ct][mt], af[ct], bf[mt]);
        }
        __syncthreads();
    }

    // ---- epilogue: bias + swish -> Zh (fp16 only) ----
    #pragma unroll
    for (int ct = 0; ct < 4; ct++) {
        int crow = c0 + warp_c * 64 + ct * 16 + (lane >> 2);
        float bv0 = (crow < C_DIM) ? __ldg(bias + crow) : 0.f;
        float bv1 = (crow + 8 < C_DIM) ? __ldg(bias + crow + 8) : 0.f;
        #pragma unroll
        for (int mt = 0; mt < 4; mt++) {
            int m = m0 + warp_m * 32 + mt * 8 + 2 * (lane & 3);
            float* d = acc[ct][mt];
            if (crow < C_DIM) {
                float z0 = swishf(d[0] + bv0), z1 = swishf(d[1] + bv0);
                *(uint32_t*)(g_Zh + (size_t)crow * N_B + m) = h2pack(z0, z1);
            }
            if (crow + 8 < C_DIM) {
                float z2 = swishf(d[2] + bv1), z3 = swishf(d[3] + bv1);
                *(uint32_t*)(g_Zh + (size_t)(crow + 8) * N_B + m) =
                    h2pack(z2, z3);
            }
        }
    }
}

// ---------------- CSR build: zero, hist, scan x3, bucket-scatter --------
__global__ void zero_cnt_kernel() {
    int i = blockIdx.x * 256 + threadIdx.x;
    if (i < C_DIM) g_cnt[i] = 0;
}

__global__ void hist_kernel(const int* __restrict__ A_rows) {
    int e = blockIdx.x * 256 + threadIdx.x;
    if (e < E_TOT) atomicAdd(&g_cnt[A_rows[e]], 1);
}

__global__ void scan1_kernel() {
    int i = blockIdx.x * 256 + threadIdx.x;
    int v = (i < C_DIM) ? g_cnt[i] : 0;
    int lane = threadIdx.x & 31, w = threadIdx.x >> 5;
    int x = v;
    #pragma unroll
    for (int o = 1; o < 32; o <<= 1) {
        int y = __shfl_up_sync(~0u, x, o);
        if (lane >= o) x += y;
    }
    __shared__ int ws[8];
    if (lane == 31) ws[w] = x;
    __syncthreads();
    if (threadIdx.x < 8) {
        int s = ws[threadIdx.x];
        #pragma unroll
        for (int o = 1; o < 8; o <<= 1) {
            int y = __shfl_up_sync(0xff, s, o);
            if ((int)threadIdx.x >= o) s += y;
        }
        ws[threadIdx.x] = s;
    }
    __syncthreads();
    int off = (w > 0) ? ws[w - 1] : 0;
    int incl = x + off;
    if (i < C_DIM) g_local[i] = incl - v;
    if (threadIdx.x == 255) g_bsum[blockIdx.x] = incl;
}

__global__ void scan2_kernel() {
    int i = threadIdx.x;
    int v = (i < NBLK_SCAN) ? g_bsum[i] : 0;
    int lane = i & 31, w = i >> 5;
    int x = v;
    #pragma unroll
    for (int o = 1; o < 32; o <<= 1) {
        int y = __shfl_up_sync(~0u, x, o);
        if (lane >= o) x += y;
    }
    __shared__ int ws[8];
    if (lane == 31) ws[w] = x;
    __syncthreads();
    if (i < 8) {
        int s = ws[i];
        #pragma unroll
        for (int o = 1; o < 8; o <<= 1) {
            int y = __shfl_up_sync(0xff, s, o);
            if (i >= o) s += y;
        }
        ws[i] = s;
    }
    __syncthreads();
    int off = (w > 0) ? ws[w - 1] : 0;
    g_boff[i] = x + off - v;
}

__global__ void scan3_kernel() {
    int i = blockIdx.x * 256 + threadIdx.x;
    if (i < C_DIM) {
        int rs = g_local[i] + g_boff[i >> 8];
        g_rowstart[i] = rs;
        g_cursor[i]   = rs;
    }
    if (i == 0) g_rowstart[C_DIM] = E_TOT;
}

__global__ void build_kernel(const float* __restrict__ A_vals,
                             const float* __restrict__ vec,
                             const int* __restrict__ A_rows,
                             const int* __restrict__ A_cols) {
    int e = blockIdx.x * 256 + threadIdx.x;
    if (e >= E_TOT) return;
    int r = A_rows[e];
    int pos = atomicAdd(&g_cursor[r], 1);
    g_epack[pos] = make_uint2((uint32_t)A_cols[e],
                              __float_as_uint(A_vals[e] * __ldg(&vec[e / NNZ_G])));
}

// -- fused SpMM + transpose-out (one n-half): warp per row, fp16 gather --
__global__ __launch_bounds__(256) void spmm_out_kernel(float* __restrict__ out,
                                                       int nhalf) {
    __shared__ float sm[8][132];
    int wid = threadIdx.x >> 5, lane = threadIdx.x & 31;
    int row = blockIdx.x * 8 + wid;
    int beg = g_rowstart[row], end = g_rowstart[row + 1];
    const uint2* E = g_epack;
    const __half* Zb = g_Zh + nhalf * 128;

    // residual Z init from fp16 image; lane covers n-local = lane*4 .. +3
    float4 acc;
    {
        uint2 h = *(const uint2*)(Zb + (size_t)row * N_B + lane * 4);
        float2 a = __half22float2(*(__half2*)&h.x);
        float2 b = __half22float2(*(__half2*)&h.y);
        acc = make_float4(a.x, a.y, b.x, b.y);
    }

    int e = beg;
    for (; e + 4 <= end; e += 4) {
        uint2 p0 = E[e], p1 = E[e + 1], p2 = E[e + 2], p3 = E[e + 3];
        uint2 h0 = *(const uint2*)(Zb + (size_t)p0.x * N_B + lane * 4);
        uint2 h1 = *(const uint2*)(Zb + (size_t)p1.x * N_B + lane * 4);
        uint2 h2 = *(const uint2*)(Zb + (size_t)p2.x * N_B + lane * 4);
        uint2 h3 = *(const uint2*)(Zb + (size_t)p3.x * N_B + lane * 4);
        float w0 = __uint_as_float(p0.y), w1 = __uint_as_float(p1.y);
        float w2 = __uint_as_float(p2.y), w3 = __uint_as_float(p3.y);
        float2 a, b;
        a = __half22float2(*(__half2*)&h0.x); b = __half22float2(*(__half2*)&h0.y);
        acc.x = fmaf(w0, a.x, acc.x); acc.y = fmaf(w0, a.y, acc.y);
        acc.z = fmaf(w0, b.x, acc.z); acc.w = fmaf(w0, b.y, acc.w);
        a = __half22float2(*(__half2*)&h1.x); b = __half22float2(*(__half2*)&h1.y);
        acc.x = fmaf(w1, a.x, acc.x); acc.y = fmaf(w1, a.y, acc.y);
        acc.z = fmaf(w1, b.x, acc.z); acc.w = fmaf(w1, b.y, acc.w);
        a = __half22float2(*(__half2*)&h2.x); b = __half22float2(*(__half2*)&h2.y);
        acc.x = fmaf(w2, a.x, acc.x); acc.y = fmaf(w2, a.y, acc.y);
        acc.z = fmaf(w2, b.x, acc.z); acc.w = fmaf(w2, b.y, acc.w);
        a = __half22float2(*(__half2*)&h3.x); b = __half22float2(*(__half2*)&h3.y);
        acc.x = fmaf(w3, a.x, acc.x); acc.y = fmaf(w3, a.y, acc.y);
        acc.z = fmaf(w3, b.x, acc.z); acc.w = fmaf(w3, b.y, acc.w);
    }
    for (; e < end; e++) {
        uint2 p = E[e];
        float w = __uint_as_float(p.y);
        uint2 h = *(const uint2*)(Zb + (size_t)p.x * N_B + lane * 4);
        float2 a = __half22float2(*(__half2*)&h.x);
        float2 b = __half22float2(*(__half2*)&h.y);
        acc.x = fmaf(w, a.x, acc.x); acc.y = fmaf(w, a.y, acc.y);
        acc.z = fmaf(w, b.x, acc.z); acc.w = fmaf(w, b.y, acc.w);
    }

    // stage sm[c_local][n_local]
    sm[wid][lane * 4 + 0] = acc.x;
    sm[wid][lane * 4 + 1] = acc.y;
    sm[wid][lane * 4 + 2] = acc.z;
    sm[wid][lane * 4 + 3] = acc.w;
    __syncthreads();

    // transposed write: thread t -> n_local = t>>1, c quad = (t&1)*4
    int nl = threadIdx.x >> 1;
    int cq = (threadIdx.x & 1) * 4;
    float4 v = make_float4(sm[cq + 0][nl], sm[cq + 1][nl],
                           sm[cq + 2][nl], sm[cq + 3][nl]);
    *(float4*)(out + (size_t)(nhalf * 128 + nl) * C_DIM + blockIdx.x * 8 + cq) = v;
}

// ------- launch: round-12 structure (2 forked streams) ------------------
extern "C" void kernel_launch(void* const* d_in, const int* in_sizes, int n_in,
                              void* d_out, int out_size) {
    const float* output = (const float*)d_in[0];
    const float* wt2_w  = (const float*)d_in[1];
    const float* wt2_b  = (const float*)d_in[2];
    const float* A_vals = (const float*)d_in[3];
    const float* vec    = (const float*)d_in[4];
    const int*   A_rows = (const int*)d_in[5];
    const int*   A_cols = (const int*)d_in[6];
    float* out = (float*)d_out;

    static cudaStream_t sCsr = nullptr, sAux = nullptr;
    static cudaEvent_t evFork = nullptr, evCsr = nullptr, evG0 = nullptr,
                       evAux = nullptr;
    if (!sCsr) {
        cudaStreamCreateWithFlags(&sCsr, cudaStreamNonBlocking);
        cudaStreamCreateWithFlags(&sAux, cudaStreamNonBlocking);
        cudaEventCreateWithFlags(&evFork, cudaEventDisableTiming);
        cudaEventCreateWithFlags(&evCsr, cudaEventDisableTiming);
        cudaEventCreateWithFlags(&evG0, cudaEventDisableTiming);
        cudaEventCreateWithFlags(&evAux, cudaEventDisableTiming);
        cudaFuncSetAttribute(mma_gemm,
                             cudaFuncAttributeMaxDynamicSharedMemorySize,
                             GEMM_SMEM);
    }

    int egrid = (E_TOT + 255) / 256;
    int wgrid = (NTILES * NCH * 128 * 8) / 256;   // 25024

    cudaEventRecord(evFork, 0);
    cudaStreamWaitEvent(sCsr, evFork, 0);

    // main stream: gemm0 at kernel index 3 for ncu
    wconv_kernel<<<wgrid, 256>>>(wt2_w);                           // 0
    stats_kernel<<<D_K / 32, 256>>>(output);                       // 1
    bconv_kernel<<<32, 256>>>(output);                             // 2
    mma_gemm<<<NTILES, 256, GEMM_SMEM>>>(wt2_b, 0);                // 3 <- ncu
    cudaEventRecord(evG0, 0);

    zero_cnt_kernel<<<NBLK_SCAN, 256, 0, sCsr>>>();
    hist_kernel<<<egrid, 256, 0, sCsr>>>(A_rows);
    scan1_kernel<<<NBLK_SCAN, 256, 0, sCsr>>>();
    scan2_kernel<<<1, 256, 0, sCsr>>>();
    scan3_kernel<<<NBLK_SCAN, 256, 0, sCsr>>>();
    build_kernel<<<egrid, 256, 0, sCsr>>>(A_vals, vec, A_rows, A_cols);
    cudaEventRecord(evCsr, sCsr);

    mma_gemm<<<NTILES, 256, GEMM_SMEM>>>(wt2_b, 128);

    // aux: half-0 sparse work overlapped with gemm half-1
    cudaStreamWaitEvent(sAux, evG0, 0);
    cudaStreamWaitEvent(sAux, evCsr, 0);
    spmm_out_kernel<<<C_DIM / 8, 256, 0, sAux>>>(out, 0);
    cudaEventRecord(evAux, sAux);

    // main: half-1 sparse work after gemm half-1
    cudaStreamWaitEvent(0, evCsr, 0);
    spmm_out_kernel<<<C_DIM / 8, 256>>>(out, 1);

    cudaStreamWaitEvent(0, evAux, 0);
}